// round 1
// baseline (speedup 1.0000x reference)
#include <cuda_runtime.h>
#include <cstdint>

#define NB      131072
#define DC      1029
#define TT      1024
#define H1N     64
#define H2N     32
#define KTOT    1028          // GEMM K: x cols 0..1027 (combined vector minus c_eff col)
#define KC      64
#define NCH     17            // 17*64 = 1088 padded K
#define MT      128           // rows per CTA
#define NT      256           // threads per CTA
#define XT_S    130           // Xt row stride (pad 2: conflict-free transpose store)

__device__ float g_row_mean[TT];
__device__ float g_w1m[NCH * KC * H1N];   // shifted+padded w1: [1088][64]

// ---------------- packed f32x2 helpers ----------------
__device__ __forceinline__ unsigned long long f32x2_dup(float v) {
    unsigned long long r;
    asm("mov.b64 %0, {%1, %2};" : "=l"(r) : "f"(v), "f"(v));
    return r;
}
__device__ __forceinline__ unsigned long long f32x2_zero() {
    return 0ull;
}
__device__ __forceinline__ void fma2(unsigned long long& d,
                                     unsigned long long a,
                                     unsigned long long b) {
    asm("fma.rn.f32x2 %0, %1, %2, %0;" : "+l"(d) : "l"(a), "l"(b));
}
__device__ __forceinline__ void unpack2(unsigned long long v, float& lo, float& hi) {
    asm("mov.b64 {%0, %1}, %2;" : "=f"(lo), "=f"(hi) : "l"(v));
}

// ---------------- prep kernel: shifted / zero-padded W1 ----------------
// combined[k] uses w1 row k for k<4, w1 row k+1 for 4<=k<1028, zero pad to 1088.
__global__ void build_w1m_kernel(const float* __restrict__ w1) {
    int idx = blockIdx.x * blockDim.x + threadIdx.x;
    if (idx >= NCH * KC * H1N) return;
    int k = idx / H1N;
    int j = idx - k * H1N;
    float v = 0.f;
    if (k < 4)          v = w1[k * H1N + j];
    else if (k < KTOT)  v = w1[(k + 1) * H1N + j];
    g_w1m[idx] = v;
}

// ---------------- prep kernel: contention row means ----------------
__global__ void row_mean_kernel(const float* __restrict__ con) {
    int t = blockIdx.x;
    float s = 0.f;
    for (int j = threadIdx.x; j < TT; j += blockDim.x)
        s += con[t * TT + j];
#pragma unroll
    for (int o = 16; o > 0; o >>= 1) s += __shfl_down_sync(0xffffffffu, s, o);
    __shared__ float red[8];
    if ((threadIdx.x & 31) == 0) red[threadIdx.x >> 5] = s;
    __syncthreads();
    if (threadIdx.x == 0) {
        float tot = 0.f;
#pragma unroll
        for (int w = 0; w < 8; w++) tot += red[w];
        g_row_mean[t] = tot * (1.0f / (float)TT);
    }
}

// ---------------- fused main kernel ----------------
struct Smem {
    float Xt[KC][XT_S];     // transposed X chunk [k][row]; reused as transposed H1 [j][row]
    float Ws[KC][H1N];      // W1 chunk
    float w2s[H1N][H2N];
    float ceff[MT];
    float amax_v[NT];
    int   amax_i[NT];
};

__global__ __launch_bounds__(NT, 3)
void fused_kernel(const float* __restrict__ x,
                  const float* __restrict__ w1,
                  const float* __restrict__ b1,
                  const float* __restrict__ w2,
                  const float* __restrict__ b2,
                  const float* __restrict__ w3,
                  const float* __restrict__ b3,
                  float* __restrict__ out)
{
    extern __shared__ char smem_raw[];
    Smem& sm = *reinterpret_cast<Smem*>(smem_raw);

    const int tid = threadIdx.x;
    const long long row0 = (long long)blockIdx.x * MT;

    // stage w2
    for (int i = tid; i < H1N * H2N; i += NT)
        (&sm.w2s[0][0])[i] = w2[i];

    // GEMM thread tile: 8 rows (as 4 f32x2 pairs) x 4 cols
    const int tr = tid >> 4;          // 0..15 -> rows tr*8 .. tr*8+7
    const int tc = tid & 15;          // 0..15 -> cols tc*4 .. tc*4+3
    // X loader mapping
    const int lrow = tid >> 4;
    const int lcol = tid & 15;
    // argmax mapping: 2 threads per row
    const int arow  = tid >> 1;
    const int abase = (tid & 1) * 32;

    unsigned long long acc2[4][4];
#pragma unroll
    for (int p = 0; p < 4; p++)
#pragma unroll
        for (int n = 0; n < 4; n++) acc2[p][n] = f32x2_zero();

    float mv = __int_as_float(0xff800000);  // -inf
    int   mi = 0;

    for (int ch = 0; ch < NCH; ch++) {
        const int kb = ch * KC;
        __syncthreads();

        // --- load W1 chunk (L2-resident) ---
        {
            const float4* src = reinterpret_cast<const float4*>(g_w1m + (size_t)kb * H1N);
            float4* dst = reinterpret_cast<float4*>(&sm.Ws[0][0]);
#pragma unroll
            for (int i = 0; i < (KC * H1N / 4) / NT; i++)
                dst[i * NT + tid] = src[i * NT + tid];
        }

        // --- stream X chunk, store transposed ---
#pragma unroll
        for (int p = 0; p < 8; p++) {
            const int r = p * 16 + lrow;
            const float* xr = x + (row0 + r) * (long long)DC;
#pragma unroll
            for (int i = 0; i < 4; i++) {
                const int k = kb + lcol + 16 * i;
                const float v = (k < KTOT) ? __ldg(xr + k) : 0.f;
                sm.Xt[lcol + 16 * i][r] = v;
            }
        }
        __syncthreads();

        // --- argmax partial over this chunk (skip k<4, k>=1028) ---
#pragma unroll 8
        for (int c = 0; c < 32; c++) {
            const int kg = kb + abase + c;
            const float v = sm.Xt[abase + c][arow];
            if (kg >= 4 && kg < KTOT && v > mv) { mv = v; mi = kg - 4; }
        }

        // --- GEMM: packed f32x2 FMAs ---
#pragma unroll 4
        for (int k = 0; k < KC; k++) {
            const float4 bv = *reinterpret_cast<const float4*>(&sm.Ws[k][tc * 4]);
            unsigned long long bd0 = f32x2_dup(bv.x);
            unsigned long long bd1 = f32x2_dup(bv.y);
            unsigned long long bd2 = f32x2_dup(bv.z);
            unsigned long long bd3 = f32x2_dup(bv.w);
            const float* xk = &sm.Xt[k][tr * 8];
#pragma unroll
            for (int p = 0; p < 4; p++) {
                const unsigned long long ap =
                    *reinterpret_cast<const unsigned long long*>(xk + 2 * p);
                fma2(acc2[p][0], ap, bd0);
                fma2(acc2[p][1], ap, bd1);
                fma2(acc2[p][2], ap, bd2);
                fma2(acc2[p][3], ap, bd3);
            }
        }
    }

    // --- argmax merge + contention effect ---
    __syncthreads();
    sm.amax_v[tid] = mv;
    sm.amax_i[tid] = mi;
    __syncthreads();
    if (tid < MT) {
        const float v0 = sm.amax_v[2 * tid],     v1 = sm.amax_v[2 * tid + 1];
        const int   i0 = sm.amax_i[2 * tid],     i1 = sm.amax_i[2 * tid + 1];
        const int best = (v1 > v0 || (v1 == v0 && i1 < i0)) ? i1 : i0;
        const float x0 = __ldg(x + (row0 + tid) * (long long)DC);  // density
        sm.ceff[tid] = g_row_mean[best] * x0;
    }
    __syncthreads();

    // --- epilogue layer 1: + c_eff*w1[4,:], +b1, relu; store H1 transposed in Xt ---
    {
        float w14[4], bb1[4];
#pragma unroll
        for (int n = 0; n < 4; n++) {
            w14[n] = __ldg(w1 + 4 * H1N + tc * 4 + n);
            bb1[n] = __ldg(b1 + tc * 4 + n);
        }
#pragma unroll
        for (int p = 0; p < 4; p++) {
            const int r0 = tr * 8 + 2 * p;
            const float ce0 = sm.ceff[r0];
            const float ce1 = sm.ceff[r0 + 1];
#pragma unroll
            for (int n = 0; n < 4; n++) {
                float lo, hi;
                unpack2(acc2[p][n], lo, hi);
                sm.Xt[tc * 4 + n][r0]     = fmaxf(lo + ce0 * w14[n] + bb1[n], 0.f);
                sm.Xt[tc * 4 + n][r0 + 1] = fmaxf(hi + ce1 * w14[n] + bb1[n], 0.f);
            }
        }
    }
    __syncthreads();

    // --- layers 2 & 3: one thread per row ---
    if (tid < MT) {
        float a2[H2N];
#pragma unroll
        for (int j = 0; j < H2N; j++) a2[j] = __ldg(b2 + j);
#pragma unroll 4
        for (int k = 0; k < H1N; k++) {
            const float a = sm.Xt[k][tid];
            const float4* w2r = reinterpret_cast<const float4*>(&sm.w2s[k][0]);
#pragma unroll
            for (int q = 0; q < H2N / 4; q++) {
                const float4 w4 = w2r[q];
                a2[q * 4 + 0] += a * w4.x;
                a2[q * 4 + 1] += a * w4.y;
                a2[q * 4 + 2] += a * w4.z;
                a2[q * 4 + 3] += a * w4.w;
            }
        }
        float o = __ldg(b3);
#pragma unroll
        for (int j = 0; j < H2N; j++)
            o += fmaxf(a2[j], 0.f) * __ldg(w3 + j);
        out[row0 + tid] = fmaxf(o, 0.f);
    }
}

// ---------------- launch ----------------
extern "C" void kernel_launch(void* const* d_in, const int* in_sizes, int n_in,
                              void* d_out, int out_size) {
    const float* x   = (const float*)d_in[0];
    const float* con = (const float*)d_in[1];
    const float* w1  = (const float*)d_in[2];
    const float* b1  = (const float*)d_in[3];
    const float* w2  = (const float*)d_in[4];
    const float* b2  = (const float*)d_in[5];
    const float* w3  = (const float*)d_in[6];
    const float* b3  = (const float*)d_in[7];
    float* out = (float*)d_out;

    cudaFuncSetAttribute(fused_kernel,
                         cudaFuncAttributeMaxDynamicSharedMemorySize,
                         (int)sizeof(Smem));

    build_w1m_kernel<<<(NCH * KC * H1N + 255) / 256, 256>>>(w1);
    row_mean_kernel<<<TT, 256>>>(con);
    fused_kernel<<<NB / MT, NT, sizeof(Smem)>>>(x, w1, b1, w2, b2, w3, b3, out);
}

// round 3
// speedup vs baseline: 1.0473x; 1.0473x over previous
#include <cuda_runtime.h>
#include <cstdint>

#define NB    131072
#define DC    1029
#define TT    1024
#define H1N   64
#define H2N   32
#define KTOT  1028
#define KC    32
#define NCH   33              // 33*32 = 1056 padded K
#define MT    128             // rows per CTA
#define NT    128             // threads per CTA (4 warps)

// A fragment block: (w,mt,kt) -> 576 bytes (4 j-planes * 128B + 64B pad for banks)
#define ABLK  576
#define A_BYTES (32 * ABLK)          // 18432
#define BST_FLOATS 2048              // 8KB per chunk of pre-packed B frags
#define H_STRIDE 68                  // floats, h row stride
#define REGION0_FLOATS (MT * H_STRIDE)   // 8704 floats = 34816B (>= A+B staging 26624B)

__device__ float g_row_mean[TT];
__device__ float g_w1f[NCH * BST_FLOATS];   // pre-packed tf32 B fragments

// ---------------- helpers ----------------
__device__ __forceinline__ uint32_t tf32r(float f) {
    uint32_t u;
    asm("cvt.rna.tf32.f32 %0, %1;" : "=r"(u) : "f"(f));
    return u;
}
__device__ __forceinline__ void mma_tf32(float* d, const uint32_t* a, const uint32_t* b) {
    asm volatile(
        "mma.sync.aligned.m16n8k8.row.col.f32.tf32.tf32.f32 "
        "{%0,%1,%2,%3}, {%4,%5,%6,%7}, {%8,%9}, {%0,%1,%2,%3};"
        : "+f"(d[0]), "+f"(d[1]), "+f"(d[2]), "+f"(d[3])
        : "r"(a[0]), "r"(a[1]), "r"(a[2]), "r"(a[3]), "r"(b[0]), "r"(b[1]));
}

// ---------------- prep: pre-packed B fragments ----------------
// idx = ((((ch*4+kt)*8+nt)*32)+lane)*2+jj
// value: B[k][n] with k = ch*32 + kt*8 + (lane&3) + jj*4, n = nt*8 + (lane>>2)
// B = shifted w1 (k<4 -> w1[k], 4<=k<1028 -> w1[k+1], else 0), tf32-rounded.
__global__ void build_w1f_kernel(const float* __restrict__ w1) {
    int idx = blockIdx.x * blockDim.x + threadIdx.x;
    if (idx >= NCH * BST_FLOATS) return;
    int jj   = idx & 1;
    int lane = (idx >> 1) & 31;
    int nt   = (idx >> 6) & 7;
    int kt   = (idx >> 9) & 3;
    int ch   = idx >> 11;
    int k = ch * 32 + kt * 8 + (lane & 3) + jj * 4;
    int n = nt * 8 + (lane >> 2);
    float v = 0.f;
    if (k < 4)          v = w1[k * H1N + n];
    else if (k < KTOT)  v = w1[(k + 1) * H1N + n];
    g_w1f[idx] = __uint_as_float(tf32r(v));
}

// ---------------- prep: contention row means ----------------
__global__ void row_mean_kernel(const float* __restrict__ con) {
    int t = blockIdx.x;
    float s = 0.f;
    for (int j = threadIdx.x; j < TT; j += blockDim.x)
        s += con[(size_t)t * TT + j];
#pragma unroll
    for (int o = 16; o > 0; o >>= 1) s += __shfl_down_sync(0xffffffffu, s, o);
    __shared__ float red[8];
    if ((threadIdx.x & 31) == 0) red[threadIdx.x >> 5] = s;
    __syncthreads();
    if (threadIdx.x == 0) {
        float tot = 0.f;
#pragma unroll
        for (int w = 0; w < 8; w++) tot += red[w];
        g_row_mean[t] = tot * (1.0f / (float)TT);
    }
}

// ---------------- fused main kernel ----------------
__global__ __launch_bounds__(NT, 4)
void fused_mma(const float* __restrict__ x,
               const float* __restrict__ w1,
               const float* __restrict__ b1,
               const float* __restrict__ w2,
               const float* __restrict__ b2,
               const float* __restrict__ w3,
               const float* __restrict__ b3,
               float* __restrict__ out)
{
    __shared__ __align__(16) float s_big[REGION0_FLOATS];  // A+B staging, later h
    __shared__ __align__(16) float s_w2[H1N * H2N];
    __shared__ float s_w14[H1N], s_b1[H1N], s_b2[H2N], s_w3[H2N];
    __shared__ float s_den[MT], s_ceff[MT];
    __shared__ int   s_mi[MT];

    const int tid  = threadIdx.x;
    const int w    = tid >> 5;
    const int lane = tid & 31;
    const int row0 = blockIdx.x * MT;

    char* Aregion = (char*)s_big;                 // 18432 B
    float* Bst    = s_big + A_BYTES / 4;          // 8192 B
    float* h      = s_big;                        // reused after main loop

    // stage constants
#pragma unroll
    for (int i = tid; i < H1N * H2N; i += NT) s_w2[i] = __ldg(w2 + i);
    if (tid < H1N) { s_w14[tid] = __ldg(w1 + 4 * H1N + tid); s_b1[tid] = __ldg(b1 + tid); }
    if (tid < H2N) { s_b2[tid] = __ldg(b2 + tid); s_w3[tid] = __ldg(w3 + tid); }

    // producer mapping
    const int lrow = tid >> 3;          // 0..15
    const int lcol = tid & 7;           // 0..7 -> cols lcol*4..+3
    const int kt_p = lcol >> 1;         // producer's kt
    const int jhi  = 2 * (lcol & 1);    // j bit1 (col>=4 within ktile)

    float amv[8];
    int   ami[8];
#pragma unroll
    for (int q = 0; q < 8; q++) { amv[q] = __int_as_float(0xff800000); ami[q] = 0; }

    float acc[2][8][4];
#pragma unroll
    for (int mt = 0; mt < 2; mt++)
#pragma unroll
        for (int nt = 0; nt < 8; nt++)
#pragma unroll
            for (int j = 0; j < 4; j++) acc[mt][nt][j] = 0.f;

    const size_t xoff0 = (size_t)(row0 + lrow) * DC + lcol * 4;

    for (int ch = 0; ch < NCH; ++ch) {
        const int kb = ch * KC;
        __syncthreads();   // previous consumers done before overwrite

        // ---- stage B fragments (8KB, contiguous copy) ----
        {
            const float4* bs = reinterpret_cast<const float4*>(g_w1f + (size_t)ch * BST_FLOATS);
            float4* bd = reinterpret_cast<float4*>(Bst);
#pragma unroll
            for (int i = 0; i < 4; i++)
                bd[i * NT + tid] = bs[i * NT + tid];
        }

        // ---- stream x chunk: argmax + tf32 + fragment-major STS.128 ----
        const int kg0 = kb + lcol * 4;
#pragma unroll
        for (int q = 0; q < 8; q++) {
            const int r = lrow + 16 * q;
            const float* xp = x + xoff0 + (size_t)q * 16 * DC + kb;
            float v0 = (kg0 + 0 < KTOT) ? __ldg(xp + 0) : 0.f;
            float v1 = (kg0 + 1 < KTOT) ? __ldg(xp + 1) : 0.f;
            float v2 = (kg0 + 2 < KTOT) ? __ldg(xp + 2) : 0.f;
            float v3 = (kg0 + 3 < KTOT) ? __ldg(xp + 3) : 0.f;

            if ((unsigned)(kg0 + 0 - 4) < 1024u && v0 > amv[q]) { amv[q] = v0; ami[q] = kg0 + 0 - 4; }
            if ((unsigned)(kg0 + 1 - 4) < 1024u && v1 > amv[q]) { amv[q] = v1; ami[q] = kg0 + 1 - 4; }
            if ((unsigned)(kg0 + 2 - 4) < 1024u && v2 > amv[q]) { amv[q] = v2; ami[q] = kg0 + 2 - 4; }
            if ((unsigned)(kg0 + 3 - 4) < 1024u && v3 > amv[q]) { amv[q] = v3; ami[q] = kg0 + 3 - 4; }

            if (ch == 0 && lcol == 0) s_den[r] = v0;   // density = x[row,0]

            const int wq  = r >> 5;
            const int mt  = (r >> 4) & 1;
            const int jlo = (r >> 3) & 1;
            const int rr7 = r & 7;
            uint4* dst = reinterpret_cast<uint4*>(
                Aregion + ((wq * 2 + mt) * 4 + kt_p) * ABLK + (jlo + jhi) * 128 + rr7 * 16);
            *dst = make_uint4(tf32r(v0), tf32r(v1), tf32r(v2), tf32r(v3));
        }
        __syncthreads();

        // ---- consume: 64 MMAs per warp ----
        char* Ab = Aregion + (size_t)w * 2 * 4 * ABLK;
        const char* Bb = (const char*)Bst;
#pragma unroll
        for (int kt = 0; kt < 4; kt++) {
            uint32_t a0[4], a1[4];
#pragma unroll
            for (int j = 0; j < 4; j++) {
                a0[j] = *reinterpret_cast<const uint32_t*>(Ab + (0 * 4 + kt) * ABLK + j * 128 + lane * 4);
                a1[j] = *reinterpret_cast<const uint32_t*>(Ab + (1 * 4 + kt) * ABLK + j * 128 + lane * 4);
            }
#pragma unroll
            for (int nt = 0; nt < 8; nt++) {
                uint32_t bf[2];
                *reinterpret_cast<uint2*>(bf) =
                    *reinterpret_cast<const uint2*>(Bb + (((kt * 8 + nt) * 32) + lane) * 8);
                mma_tf32(acc[0][nt], a0, bf);
                mma_tf32(acc[1][nt], a1, bf);
            }
        }
    }

    // ---- argmax reduce across the 8 lcol lanes (contiguous in lane) ----
#pragma unroll
    for (int d = 1; d < 8; d <<= 1) {
#pragma unroll
        for (int q = 0; q < 8; q++) {
            float ov = __shfl_xor_sync(0xffffffffu, amv[q], d);
            int   oi = __shfl_xor_sync(0xffffffffu, ami[q], d);
            if (ov > amv[q] || (ov == amv[q] && oi < ami[q])) { amv[q] = ov; ami[q] = oi; }
        }
    }
    if (lcol == 0) {
#pragma unroll
        for (int q = 0; q < 8; q++) s_mi[lrow + 16 * q] = ami[q];
    }
    __syncthreads();
    s_ceff[tid] = g_row_mean[s_mi[tid]] * s_den[tid];
    __syncthreads();

    // ---- layer-1 epilogue: + ceff*w1[4,:] + b1, relu; write h[row][col] ----
    {
        const int rb = w * 32 + (lane >> 2);
        const int cb = (lane & 3) * 2;
#pragma unroll
        for (int mt = 0; mt < 2; mt++) {
            const int r0 = rb + mt * 16;
            const float ce0 = s_ceff[r0];
            const float ce1 = s_ceff[r0 + 8];
#pragma unroll
            for (int nt = 0; nt < 8; nt++) {
                const int c = nt * 8 + cb;
                const float w140 = s_w14[c],     w141 = s_w14[c + 1];
                const float bb0  = s_b1[c],      bb1  = s_b1[c + 1];
                float2 top, bot;
                top.x = fmaxf(acc[mt][nt][0] + ce0 * w140 + bb0, 0.f);
                top.y = fmaxf(acc[mt][nt][1] + ce0 * w141 + bb1, 0.f);
                bot.x = fmaxf(acc[mt][nt][2] + ce1 * w140 + bb0, 0.f);
                bot.y = fmaxf(acc[mt][nt][3] + ce1 * w141 + bb1, 0.f);
                *reinterpret_cast<float2*>(h + (size_t)r0 * H_STRIDE + c) = top;
                *reinterpret_cast<float2*>(h + (size_t)(r0 + 8) * H_STRIDE + c) = bot;
            }
        }
    }
    __syncthreads();

    // ---- layers 2 & 3: one thread per row ----
    {
        float a2[H2N];
#pragma unroll
        for (int j = 0; j < H2N; j++) a2[j] = s_b2[j];
        const float* hr = h + (size_t)tid * H_STRIDE;
#pragma unroll 4
        for (int k = 0; k < H1N; k++) {
            const float a = hr[k];
            const float4* w2r = reinterpret_cast<const float4*>(s_w2 + k * H2N);
#pragma unroll
            for (int qq = 0; qq < H2N / 4; qq++) {
                float4 w4 = w2r[qq];
                a2[qq * 4 + 0] += a * w4.x;
                a2[qq * 4 + 1] += a * w4.y;
                a2[qq * 4 + 2] += a * w4.z;
                a2[qq * 4 + 3] += a * w4.w;
            }
        }
        float o = __ldg(b3);
#pragma unroll
        for (int j = 0; j < H2N; j++)
            o += fmaxf(a2[j], 0.f) * s_w3[j];
        out[row0 + tid] = fmaxf(o, 0.f);
    }
}

// ---------------- launch ----------------
extern "C" void kernel_launch(void* const* d_in, const int* in_sizes, int n_in,
                              void* d_out, int out_size) {
    const float* x   = (const float*)d_in[0];
    const float* con = (const float*)d_in[1];
    const float* w1  = (const float*)d_in[2];
    const float* b1  = (const float*)d_in[3];
    const float* w2  = (const float*)d_in[4];
    const float* b2  = (const float*)d_in[5];
    const float* w3  = (const float*)d_in[6];
    const float* b3  = (const float*)d_in[7];
    float* out = (float*)d_out;

    build_w1f_kernel<<<(NCH * BST_FLOATS + 255) / 256, 256>>>(w1);
    row_mean_kernel<<<TT, 256>>>(con);
    fused_mma<<<NB / MT, NT>>>(x, w1, b1, w2, b2, w3, b3, out);
}

// round 4
// speedup vs baseline: 1.5658x; 1.4951x over previous
#include <cuda_runtime.h>
#include <cstdint>

#define NB    131072
#define DC    1029
#define TT    1024
#define H1N   64
#define H2N   32
#define KTOT  1028
#define KC    32
#define NCH   33              // 33*32 = 1056 padded K
#define MT    128             // rows per CTA
#define NT    256             // threads per CTA (8 warps)
#define NSTG  4
#define A_ST  16384           // 128 rows * 128B
#define B_ST  8192            // 2048 floats of packed B frags
#define STG   (A_ST + B_ST)   // 24576
#define SMEM_DYN (NSTG * STG) // 98304
#define H_STRIDE 68

__device__ float g_row_mean[TT];
__device__ __align__(16) float g_w1f[NCH * 2048];   // pre-packed tf32 B fragments

// ---------------- helpers ----------------
__device__ __forceinline__ uint32_t tf32r(float f) {
    uint32_t u;
    asm("cvt.rna.tf32.f32 %0, %1;" : "=r"(u) : "f"(f));
    return u;
}
__device__ __forceinline__ void mma_tf32(float* d, const uint32_t* a, const uint32_t* b) {
    asm volatile(
        "mma.sync.aligned.m16n8k8.row.col.f32.tf32.tf32.f32 "
        "{%0,%1,%2,%3}, {%4,%5,%6,%7}, {%8,%9}, {%0,%1,%2,%3};"
        : "+f"(d[0]), "+f"(d[1]), "+f"(d[2]), "+f"(d[3])
        : "r"(a[0]), "r"(a[1]), "r"(a[2]), "r"(a[3]), "r"(b[0]), "r"(b[1]));
}
__device__ __forceinline__ uint32_t smem_u32(const void* p) {
    uint32_t a;
    asm("{ .reg .u64 t; cvta.to.shared.u64 t, %1; cvt.u32.u64 %0, t; }" : "=r"(a) : "l"(p));
    return a;
}
__device__ __forceinline__ void cp4(uint32_t dst, const float* src) {
    asm volatile("cp.async.ca.shared.global [%0], [%1], 4;"
                 :: "r"(dst), "l"(__cvta_generic_to_global(src)) : "memory");
}
__device__ __forceinline__ void cp16(uint32_t dst, const float* src) {
    asm volatile("cp.async.ca.shared.global [%0], [%1], 16;"
                 :: "r"(dst), "l"(__cvta_generic_to_global(src)) : "memory");
}

// ---------------- merged prep kernel ----------------
// blocks [0, TT): contention row means.  blocks [TT, ...): pack B fragments.
// pack idx = ((((ch*4+kt)*8+nt)*32)+lane)*2+jj ;
//   k = ch*32 + kt*8 + (lane&3) + jj*4, n = nt*8 + (lane>>2)
__global__ void prep_kernel(const float* __restrict__ con, const float* __restrict__ w1) {
    if (blockIdx.x < TT) {
        int t = blockIdx.x;
        float s = 0.f;
        for (int j = threadIdx.x; j < TT; j += blockDim.x)
            s += con[(size_t)t * TT + j];
#pragma unroll
        for (int o = 16; o > 0; o >>= 1) s += __shfl_down_sync(0xffffffffu, s, o);
        __shared__ float red[8];
        if ((threadIdx.x & 31) == 0) red[threadIdx.x >> 5] = s;
        __syncthreads();
        if (threadIdx.x == 0) {
            float tot = 0.f;
#pragma unroll
            for (int w = 0; w < 8; w++) tot += red[w];
            g_row_mean[t] = tot * (1.0f / (float)TT);
        }
    } else {
        int idx = (blockIdx.x - TT) * blockDim.x + threadIdx.x;
        if (idx >= NCH * 2048) return;
        int jj   = idx & 1;
        int lane = (idx >> 1) & 31;
        int nt   = (idx >> 6) & 7;
        int kt   = (idx >> 9) & 3;
        int ch   = idx >> 11;
        int k = ch * 32 + kt * 8 + (lane & 3) + jj * 4;
        int n = nt * 8 + (lane >> 2);
        float v = 0.f;
        if (k < 4)          v = w1[k * H1N + n];
        else if (k < KTOT)  v = w1[(k + 1) * H1N + n];
        g_w1f[idx] = __uint_as_float(tf32r(v));
    }
}

// ---------------- fused main kernel ----------------
__global__ __launch_bounds__(NT, 2)
void fused_mma(const float* __restrict__ x,
               const float* __restrict__ w1,
               const float* __restrict__ b1,
               const float* __restrict__ w2,
               const float* __restrict__ b2,
               const float* __restrict__ w3,
               const float* __restrict__ b3,
               float* __restrict__ out)
{
    extern __shared__ __align__(16) char smem[];
    __shared__ __align__(16) float s_w2[H1N * H2N];
    __shared__ float s_w14[H1N], s_b1[H1N], s_b2[H2N], s_w3[H2N];
    __shared__ float s_den[MT], s_ceff[MT];
    __shared__ int   s_mi[MT];

    const uint32_t sdyn = smem_u32(smem);
    const int tid  = threadIdx.x;
    const int w    = tid >> 5;
    const int lane = tid & 31;
    const int row0 = blockIdx.x * MT;

    // stage constants
#pragma unroll
    for (int i = tid; i < H1N * H2N; i += NT) s_w2[i] = __ldg(w2 + i);
    if (tid < H1N) { s_w14[tid] = __ldg(w1 + 4 * H1N + tid); s_b1[tid] = __ldg(b1 + tid); }
    if (tid < H2N) { s_b2[tid] = __ldg(b2 + tid); s_w3[tid] = __ldg(w3 + tid); }

    // ---- producer: issue one chunk into its ring slot ----
    auto produce = [&](int ch) {
        if (ch < NCH) {
            const uint32_t slot = sdyn + (uint32_t)(ch & (NSTG - 1)) * STG;
            const int kb = ch * KC;
            // A: 4096 x 4B, swizzled 16B granules
#pragma unroll
            for (int i = 0; i < 16; i++) {
                const int idx = i * NT + tid;
                const int rl = idx >> 5;
                const int c4 = idx & 31;
                const int kg = kb + c4;
                if (kg < KTOT) {
                    const uint32_t d = slot + (uint32_t)rl * 128u
                                     + (uint32_t)(((c4 >> 2) ^ (rl & 7)) << 4)
                                     + (uint32_t)((c4 & 3) << 2);
                    cp4(d, x + (size_t)(row0 + rl) * DC + kg);
                }
            }
            // B: 512 x 16B, contiguous
#pragma unroll
            for (int i = 0; i < 2; i++) {
                const int idx = i * NT + tid;
                cp16(slot + A_ST + (uint32_t)idx * 16u,
                     g_w1f + (size_t)ch * 2048 + (size_t)idx * 4);
            }
        }
        asm volatile("cp.async.commit_group;" ::: "memory");
    };

    float amv[2];
    int   ami[2];
    amv[0] = amv[1] = __int_as_float(0xff800000);
    ami[0] = ami[1] = 0;

    float acc[8][4];
#pragma unroll
    for (int nt = 0; nt < 8; nt++)
#pragma unroll
        for (int j = 0; j < 4; j++) acc[nt][j] = 0.f;

    // prologue: fill NSTG-1 stages
    produce(0);
    produce(1);
    produce(2);

    const int rA = (lane >> 2);        // fragment sub-row
    const int cA = (lane & 3);         // fragment sub-col

    for (int ch = 0; ch < NCH; ++ch) {
        asm volatile("cp.async.wait_group 2;" ::: "memory");
        __syncthreads();               // chunk ch visible; slot (ch-1)&3 free

        produce(ch + NSTG - 1);

        const uint32_t slot = sdyn + (uint32_t)(ch & (NSTG - 1)) * STG;
        const int kb = ch * KC;

#pragma unroll
        for (int kt = 0; kt < 4; kt++) {
            uint32_t a[4];
#pragma unroll
            for (int jj = 0; jj < 4; jj++) {
                const int rl = w * 16 + rA + 8 * (jj & 1);
                const int g  = kt * 2 + (jj >> 1);
                const uint32_t addr = slot + (uint32_t)rl * 128u
                                    + (uint32_t)((g ^ (rl & 7)) << 4)
                                    + (uint32_t)(cA << 2);
                float v;
                asm volatile("ld.shared.f32 %0, [%1];" : "=f"(v) : "r"(addr));
                const int kg = kb + kt * 8 + cA + 4 * (jj >> 1);
                const int hf = jj & 1;
                if ((unsigned)(kg - 4) < 1024u && v > amv[hf]) { amv[hf] = v; ami[hf] = kg - 4; }
                if (ch == 0 && kt == 0 && (jj >> 1) == 0 && cA == 0) s_den[rl] = v;
                a[jj] = tf32r(v);
            }
#pragma unroll
            for (int nt = 0; nt < 8; nt++) {
                uint32_t bf[2];
                const uint32_t baddr = slot + A_ST
                                     + (uint32_t)((((kt * 8 + nt) * 32) + lane) * 8);
                asm volatile("ld.shared.v2.u32 {%0,%1}, [%2];"
                             : "=r"(bf[0]), "=r"(bf[1]) : "r"(baddr));
                mma_tf32(acc[nt], a, bf);
            }
        }
    }

    // ---- argmax reduce across the 4 lanes sharing a row ----
    __syncthreads();
#pragma unroll
    for (int d = 1; d < 4; d <<= 1) {
#pragma unroll
        for (int hf = 0; hf < 2; hf++) {
            float ov = __shfl_xor_sync(0xffffffffu, amv[hf], d);
            int   oi = __shfl_xor_sync(0xffffffffu, ami[hf], d);
            if (ov > amv[hf] || (ov == amv[hf] && oi < ami[hf])) { amv[hf] = ov; ami[hf] = oi; }
        }
    }
    if (cA == 0) {
        s_mi[w * 16 + rA]     = ami[0];
        s_mi[w * 16 + rA + 8] = ami[1];
    }
    __syncthreads();
    if (tid < MT) s_ceff[tid] = g_row_mean[s_mi[tid]] * s_den[tid];
    __syncthreads();

    // ---- layer-1 epilogue: +ceff*w1[4,:]+b1, relu; h -> ring smem (now free) ----
    float* h = (float*)smem;
    {
        const int r1 = w * 16 + rA;
        const int cb = cA * 2;
        const float ce0 = s_ceff[r1];
        const float ce1 = s_ceff[r1 + 8];
#pragma unroll
        for (int nt = 0; nt < 8; nt++) {
            const int c = nt * 8 + cb;
            const float w0 = s_w14[c], w1v = s_w14[c + 1];
            const float q0 = s_b1[c],  q1  = s_b1[c + 1];
            float2 top, bot;
            top.x = fmaxf(acc[nt][0] + ce0 * w0 + q0, 0.f);
            top.y = fmaxf(acc[nt][1] + ce0 * w1v + q1, 0.f);
            bot.x = fmaxf(acc[nt][2] + ce1 * w0 + q0, 0.f);
            bot.y = fmaxf(acc[nt][3] + ce1 * w1v + q1, 0.f);
            *reinterpret_cast<float2*>(h + (size_t)r1 * H_STRIDE + c) = top;
            *reinterpret_cast<float2*>(h + (size_t)(r1 + 8) * H_STRIDE + c) = bot;
        }
    }
    __syncthreads();

    // ---- layers 2 & 3: one thread per row ----
    if (tid < MT) {
        float a2[H2N];
#pragma unroll
        for (int j = 0; j < H2N; j++) a2[j] = s_b2[j];
        const float* hr = h + (size_t)tid * H_STRIDE;
#pragma unroll 4
        for (int k = 0; k < H1N; k++) {
            const float a = hr[k];
            const float4* w2r = reinterpret_cast<const float4*>(s_w2 + k * H2N);
#pragma unroll
            for (int qq = 0; qq < H2N / 4; qq++) {
                float4 w4 = w2r[qq];
                a2[qq * 4 + 0] += a * w4.x;
                a2[qq * 4 + 1] += a * w4.y;
                a2[qq * 4 + 2] += a * w4.z;
                a2[qq * 4 + 3] += a * w4.w;
            }
        }
        float o = __ldg(b3);
#pragma unroll
        for (int j = 0; j < H2N; j++)
            o += fmaxf(a2[j], 0.f) * s_w3[j];
        out[row0 + tid] = fmaxf(o, 0.f);
    }
}

// ---------------- launch (2 launches per call -> ncu -s 5 hits fused_mma) ----------------
extern "C" void kernel_launch(void* const* d_in, const int* in_sizes, int n_in,
                              void* d_out, int out_size) {
    const float* x   = (const float*)d_in[0];
    const float* con = (const float*)d_in[1];
    const float* w1  = (const float*)d_in[2];
    const float* b1  = (const float*)d_in[3];
    const float* w2  = (const float*)d_in[4];
    const float* b2  = (const float*)d_in[5];
    const float* w3  = (const float*)d_in[6];
    const float* b3  = (const float*)d_in[7];
    float* out = (float*)d_out;

    cudaFuncSetAttribute(fused_mma, cudaFuncAttributeMaxDynamicSharedMemorySize, SMEM_DYN);

    prep_kernel<<<TT + (NCH * 2048 + 255) / 256, 256>>>(con, w1);
    fused_mma<<<NB / MT, NT, SMEM_DYN>>>(x, w1, b1, w2, b2, w3, b3, out);
}

// round 5
// speedup vs baseline: 2.0886x; 1.3339x over previous
#include <cuda_runtime.h>
#include <cstdint>

#define NB    131072
#define DC    1029
#define TT    1024
#define H1N   64
#define H2N   32
#define KTOT  1028
#define KC    32
#define NCH   33              // 33*32 = 1056 padded K
#define MT    128             // rows per CTA
#define NT    256             // threads per CTA (8 warps)
#define NSTG  4
#define B_ST  8192            // bytes per B stage (2048 floats)
#define SMEM_DYN 34816        // max(B ring 32768, h staging 128*68*4)
#define H_STRIDE 68

__device__ float g_row_mean[TT];
__device__ __align__(16) float g_w1f[NCH * 2048];   // pre-packed, pre-swizzled tf32 B frags

// ---------------- helpers ----------------
__device__ __forceinline__ uint32_t tf32r(float f) {
    uint32_t u;
    asm("cvt.rna.tf32.f32 %0, %1;" : "=r"(u) : "f"(f));
    return u;
}
__device__ __forceinline__ void mma_tf32(float* d, const uint32_t* a, uint32_t b0, uint32_t b1) {
    asm volatile(
        "mma.sync.aligned.m16n8k8.row.col.f32.tf32.tf32.f32 "
        "{%0,%1,%2,%3}, {%4,%5,%6,%7}, {%8,%9}, {%0,%1,%2,%3};"
        : "+f"(d[0]), "+f"(d[1]), "+f"(d[2]), "+f"(d[3])
        : "r"(a[0]), "r"(a[1]), "r"(a[2]), "r"(a[3]), "r"(b0), "r"(b1));
}
__device__ __forceinline__ uint32_t smem_u32(const void* p) {
    uint32_t a;
    asm("{ .reg .u64 t; cvta.to.shared.u64 t, %1; cvt.u32.u64 %0, t; }" : "=r"(a) : "l"(p));
    return a;
}
__device__ __forceinline__ void cp16(uint32_t dst, const float* src) {
    asm volatile("cp.async.ca.shared.global [%0], [%1], 16;"
                 :: "r"(dst), "l"(__cvta_generic_to_global(src)) : "memory");
}

// ---------------- merged prep kernel ----------------
// blocks [0, TT): contention row means.
// blocks [TT, ..): pack B frags, swizzled granule layout:
//   float index w in chunk ch: granule g = w>>2 (16B), elem e = w&3
//   kt = g>>7, lane = (g>>2)&31, s = g&3, i = s ^ (lane&3) ^ ((lane>>2)&1)
//   nt = 2*i + (e>>1), jj = e&1
//   value = Bshift[k = ch*32 + kt*8 + (lane&3) + jj*4][n = nt*8 + (lane>>2)]
__global__ void prep_kernel(const float* __restrict__ con, const float* __restrict__ w1) {
    if (blockIdx.x < TT) {
        int t = blockIdx.x;
        float s = 0.f;
        for (int j = threadIdx.x; j < TT; j += blockDim.x)
            s += con[(size_t)t * TT + j];
#pragma unroll
        for (int o = 16; o > 0; o >>= 1) s += __shfl_down_sync(0xffffffffu, s, o);
        __shared__ float red[8];
        if ((threadIdx.x & 31) == 0) red[threadIdx.x >> 5] = s;
        __syncthreads();
        if (threadIdx.x == 0) {
            float tot = 0.f;
#pragma unroll
            for (int w = 0; w < 8; w++) tot += red[w];
            g_row_mean[t] = tot * (1.0f / (float)TT);
        }
    } else {
        int idx = (blockIdx.x - TT) * blockDim.x + threadIdx.x;
        if (idx >= NCH * 2048) return;
        int ch = idx >> 11;
        int w  = idx & 2047;
        int g  = w >> 2, e = w & 3;
        int kt = g >> 7;
        int lane = (g >> 2) & 31;
        int s = g & 3;
        int i = s ^ (lane & 3) ^ ((lane >> 2) & 1);
        int nt = 2 * i + (e >> 1);
        int jj = e & 1;
        int k = ch * 32 + kt * 8 + (lane & 3) + jj * 4;
        int n = nt * 8 + (lane >> 2);
        float v = 0.f;
        if (k < 4)          v = w1[k * H1N + n];
        else if (k < KTOT)  v = w1[(k + 1) * H1N + n];
        g_w1f[idx] = __uint_as_float(tf32r(v));
    }
}

// ---------------- fused main kernel ----------------
__global__ __launch_bounds__(NT, 2)
void fused_mma(const float* __restrict__ x,
               const float* __restrict__ w1,
               const float* __restrict__ b1,
               const float* __restrict__ w2,
               const float* __restrict__ b2,
               const float* __restrict__ w3,
               const float* __restrict__ b3,
               float* __restrict__ out)
{
    extern __shared__ __align__(16) char smem[];
    __shared__ __align__(16) float s_w2[H1N * H2N];
    __shared__ float s_w14[H1N], s_b1[H1N], s_b2[H2N], s_w3[H2N];
    __shared__ float s_den[MT], s_ceff[MT];
    __shared__ int   s_mi[MT];

    const uint32_t sdyn = smem_u32(smem);
    const int tid  = threadIdx.x;
    const int w    = tid >> 5;
    const int lane = tid & 31;
    const int rA   = lane >> 2;
    const int cA   = lane & 3;
    const int row0 = blockIdx.x * MT;

    // stage constants
#pragma unroll
    for (int i = tid; i < H1N * H2N; i += NT) s_w2[i] = __ldg(w2 + i);
    if (tid < H1N) { s_w14[tid] = __ldg(w1 + 4 * H1N + tid); s_b1[tid] = __ldg(b1 + tid); }
    if (tid < H2N) { s_b2[tid] = __ldg(b2 + tid); s_w3[tid] = __ldg(w3 + tid); }

    // B producer: 2 cp16 per thread per chunk (identity copy, pre-swizzled)
    auto produceB = [&](int ch) {
        if (ch < NCH) {
            const uint32_t slot = sdyn + (uint32_t)(ch & (NSTG - 1)) * B_ST;
            const float* src = g_w1f + (size_t)ch * 2048;
            cp16(slot + (uint32_t)tid * 16u, src + (size_t)tid * 4);
            cp16(slot + (uint32_t)(tid + NT) * 16u, src + (size_t)(tid + NT) * 4);
        }
        asm volatile("cp.async.commit_group;" ::: "memory");
    };

    // A loader: 16 floats (frag layout: idx = kt*4 + h*2 + r)
    const float* xp0 = x + (size_t)(row0 + w * 16 + rA) * DC + cA;
    const float* xp1 = xp0 + 8 * (size_t)DC;
    auto loadA = [&](int ch, float* dst) {
        const int kb = ch * KC;
#pragma unroll
        for (int kt = 0; kt < 4; kt++)
#pragma unroll
            for (int h = 0; h < 2; h++) {
                const int kg = kb + kt * 8 + h * 4;   // + cA baked into pointer
                const bool ok = (kg + cA) < KTOT;
                dst[kt * 4 + h * 2 + 0] = ok ? __ldg(xp0 + kg) : 0.f;
                dst[kt * 4 + h * 2 + 1] = ok ? __ldg(xp1 + kg) : 0.f;
            }
    };

    float amv[2];
    int   ami[2];
    amv[0] = amv[1] = __int_as_float(0xff800000);
    ami[0] = ami[1] = 0;

    float acc[8][4];
#pragma unroll
    for (int nt = 0; nt < 8; nt++)
#pragma unroll
        for (int j = 0; j < 4; j++) acc[nt][j] = 0.f;

    // prologue
    produceB(0);
    produceB(1);
    produceB(2);
    float cur[16], nxt[16];
    loadA(0, cur);

    for (int ch = 0; ch < NCH; ++ch) {
        asm volatile("cp.async.wait_group 2;" ::: "memory");
        __syncthreads();              // B(ch) visible; slot (ch-1)&3 drained by all warps

        if (ch + 1 < NCH) loadA(ch + 1, nxt);   // prefetch A into regs
        produceB(ch + 3);                        // refill ring

        // argmax + density from cur (original f32 values)
        const int kb = ch * KC;
#pragma unroll
        for (int kt = 0; kt < 4; kt++)
#pragma unroll
            for (int h = 0; h < 2; h++) {
                const int kg = kb + kt * 8 + cA + h * 4;
                const float v0 = cur[kt * 4 + h * 2 + 0];
                const float v1 = cur[kt * 4 + h * 2 + 1];
                if ((unsigned)(kg - 4) < 1024u) {
                    if (v0 > amv[0]) { amv[0] = v0; ami[0] = kg - 4; }
                    if (v1 > amv[1]) { amv[1] = v1; ami[1] = kg - 4; }
                }
            }
        if (ch == 0 && cA == 0) {
            s_den[w * 16 + rA]     = cur[0];
            s_den[w * 16 + rA + 8] = cur[1];
        }

        // convert in place to tf32
        uint32_t au[16];
#pragma unroll
        for (int i = 0; i < 16; i++) au[i] = tf32r(cur[i]);

        // MMAs: B via conflict-free LDS.128
        const uint32_t slot = sdyn + (uint32_t)(ch & (NSTG - 1)) * B_ST;
        const uint32_t bbase = slot + (uint32_t)lane * 64u;
        const int sw = (cA ^ ((lane >> 2) & 1));
#pragma unroll
        for (int kt = 0; kt < 4; kt++) {
            const uint32_t* a = au + kt * 4;
#pragma unroll
            for (int i = 0; i < 4; i++) {
                uint4 q;
                const uint32_t baddr = bbase + (uint32_t)kt * 2048u
                                     + (uint32_t)((i ^ sw) << 4);
                asm volatile("ld.shared.v4.u32 {%0,%1,%2,%3}, [%4];"
                             : "=r"(q.x), "=r"(q.y), "=r"(q.z), "=r"(q.w) : "r"(baddr));
                mma_tf32(acc[2 * i + 0], a, q.x, q.y);
                mma_tf32(acc[2 * i + 1], a, q.z, q.w);
            }
        }

#pragma unroll
        for (int i = 0; i < 16; i++) cur[i] = nxt[i];
    }

    // ---- argmax reduce across the 4 cA lanes ----
    __syncthreads();
#pragma unroll
    for (int d = 1; d < 4; d <<= 1) {
#pragma unroll
        for (int hf = 0; hf < 2; hf++) {
            float ov = __shfl_xor_sync(0xffffffffu, amv[hf], d);
            int   oi = __shfl_xor_sync(0xffffffffu, ami[hf], d);
            if (ov > amv[hf] || (ov == amv[hf] && oi < ami[hf])) { amv[hf] = ov; ami[hf] = oi; }
        }
    }
    if (cA == 0) {
        s_mi[w * 16 + rA]     = ami[0];
        s_mi[w * 16 + rA + 8] = ami[1];
    }
    __syncthreads();
    if (tid < MT) s_ceff[tid] = g_row_mean[s_mi[tid]] * s_den[tid];
    __syncthreads();

    // ---- layer-1 epilogue: +ceff*w1[4,:]+b1, relu; h -> dynamic smem (ring now free) ----
    float* h = (float*)smem;
    {
        const int r1 = w * 16 + rA;
        const int cb = cA * 2;
        const float ce0 = s_ceff[r1];
        const float ce1 = s_ceff[r1 + 8];
#pragma unroll
        for (int nt = 0; nt < 8; nt++) {
            const int c = nt * 8 + cb;
            const float w0 = s_w14[c], w1v = s_w14[c + 1];
            const float q0 = s_b1[c],  q1  = s_b1[c + 1];
            float2 top, bot;
            top.x = fmaxf(acc[nt][0] + ce0 * w0 + q0, 0.f);
            top.y = fmaxf(acc[nt][1] + ce0 * w1v + q1, 0.f);
            bot.x = fmaxf(acc[nt][2] + ce1 * w0 + q0, 0.f);
            bot.y = fmaxf(acc[nt][3] + ce1 * w1v + q1, 0.f);
            *reinterpret_cast<float2*>(h + (size_t)r1 * H_STRIDE + c) = top;
            *reinterpret_cast<float2*>(h + (size_t)(r1 + 8) * H_STRIDE + c) = bot;
        }
    }
    __syncthreads();

    // ---- layers 2 & 3: one thread per row ----
    if (tid < MT) {
        float a2[H2N];
#pragma unroll
        for (int j = 0; j < H2N; j++) a2[j] = s_b2[j];
        const float* hr = h + (size_t)tid * H_STRIDE;
#pragma unroll 4
        for (int k = 0; k < H1N; k++) {
            const float a = hr[k];
            const float4* w2r = reinterpret_cast<const float4*>(s_w2 + k * H2N);
#pragma unroll
            for (int qq = 0; qq < H2N / 4; qq++) {
                float4 w4 = w2r[qq];
                a2[qq * 4 + 0] += a * w4.x;
                a2[qq * 4 + 1] += a * w4.y;
                a2[qq * 4 + 2] += a * w4.z;
                a2[qq * 4 + 3] += a * w4.w;
            }
        }
        float o = __ldg(b3);
#pragma unroll
        for (int j = 0; j < H2N; j++)
            o += fmaxf(a2[j], 0.f) * s_w3[j];
        out[row0 + tid] = fmaxf(o, 0.f);
    }
}

// ---------------- launch (2 launches per call) ----------------
extern "C" void kernel_launch(void* const* d_in, const int* in_sizes, int n_in,
                              void* d_out, int out_size) {
    const float* x   = (const float*)d_in[0];
    const float* con = (const float*)d_in[1];
    const float* w1  = (const float*)d_in[2];
    const float* b1  = (const float*)d_in[3];
    const float* w2  = (const float*)d_in[4];
    const float* b2  = (const float*)d_in[5];
    const float* w3  = (const float*)d_in[6];
    const float* b3  = (const float*)d_in[7];
    float* out = (float*)d_out;

    cudaFuncSetAttribute(fused_mma, cudaFuncAttributeMaxDynamicSharedMemorySize, SMEM_DYN);

    prep_kernel<<<TT + (NCH * 2048 + 255) / 256, 256>>>(con, w1);
    fused_mma<<<NB / MT, NT, SMEM_DYN>>>(x, w1, b1, w2, b2, w3, b3, out);
}